// round 16
// baseline (speedup 1.0000x reference)
#include <cuda_runtime.h>
#include <math.h>

#define MAX_EDGES 100000

__device__ float g_scores[MAX_EDGES];
__device__ unsigned long long g_key;    // [sortable(logit):32 | ~idx:32], init 0
__device__ float g_sumexp;              // init 0; finalize resets both

// ---------------------------------------------------------------------------
// Kernel 1: s[e] = dot(edge_emb[e,:256], W)   [frozen winner]
// 2 edges/warp, smem-staged W, lane map {lane, lane+32}.
// ---------------------------------------------------------------------------
__global__ void __launch_bounds__(256) score_kernel(
        const float* __restrict__ emb,
        const float* __restrict__ W,
        float* __restrict__ s,
        int n_edges) {
    __shared__ float4 sw[64];

    int t    = threadIdx.x;
    int lane = t & 31;
    int warp = (blockIdx.x * blockDim.x + t) >> 5;
    int e0 = warp * 2;

    if (t < 64) sw[t] = reinterpret_cast<const float4*>(W)[t];
    __syncthreads();

    if (e0 < n_edges) {
        float4 w0 = sw[lane];
        float4 w1 = sw[lane + 32];

        const float4* p0 = reinterpret_cast<const float4*>(emb + (size_t)e0 * 256);
        const float4* p1 = p0 + 64;

        float4 a0 = p0[lane];
        float4 a1 = p0[lane + 32];
        float4 b0 = p1[lane];
        float4 b1 = p1[lane + 32];

        float accA = a0.x*w0.x + a0.y*w0.y + a0.z*w0.z + a0.w*w0.w
                   + a1.x*w1.x + a1.y*w1.y + a1.z*w1.z + a1.w*w1.w;
        float accB = b0.x*w0.x + b0.y*w0.y + b0.z*w0.z + b0.w*w0.w
                   + b1.x*w1.x + b1.y*w1.y + b1.z*w1.z + b1.w*w1.w;

        #pragma unroll
        for (int o = 16; o; o >>= 1) {
            accA += __shfl_xor_sync(0xFFFFFFFFu, accA, o);
            accB += __shfl_xor_sync(0xFFFFFFFFu, accB, o);
        }

        if (lane == 0) {
            s[e0] = accA;
            if (e0 + 1 < n_edges) s[e0 + 1] = accB;
        }
    }

    cudaTriggerProgrammaticLaunchCompletion();
}

// sortable encoding: preserves float order as unsigned order
__device__ __forceinline__ unsigned int f2sortable(float f) {
    unsigned int u = __float_as_uint(f);
    return (u & 0x80000000u) ? ~u : (u | 0x80000000u);
}
__device__ __forceinline__ float sortable2f(unsigned int u) {
    u = (u & 0x80000000u) ? (u & 0x7FFFFFFFu) : ~u;
    return __uint_as_float(u);
}

// ---------------------------------------------------------------------------
// Kernel 2 (PDL secondary of score): logits + warp reduce, then block-level
// aggregation to ONE atomicMax + ONE atomicAdd per block (79 total instead
// of 632 — the same-address L2 atomic chain serializes, so 8x fewer ops).
// ---------------------------------------------------------------------------
__global__ void __launch_bounds__(256) logits_kernel(
        const int* __restrict__ paths,
        const int* __restrict__ path_lens,
        const int* __restrict__ path_mask,
        const float* __restrict__ s,
        const float* __restrict__ b,
        int n_paths, int max_len) {
    __shared__ unsigned long long skey[8];
    __shared__ float sex[8];

    int t = threadIdx.x;
    int i = blockIdx.x * 256 + t;
    bool live = (i < n_paths);

    // preamble: score-independent loads (overlap primary via PDL)
    int4 r0 = make_int4(0,0,0,0), r1 = r0, r2 = r0, r3 = r0;
    int  my_len = 1, my_mask = 0;
    float bias = 0.0f;
    if (live) {
        const int4* row = reinterpret_cast<const int4*>(paths + (size_t)i * max_len);
        r0 = row[0]; r1 = row[1]; r2 = row[2]; r3 = row[3];
        my_len  = path_lens[i] + 1;
        my_mask = path_mask[i];
        bias    = b[0];
    }

    cudaGridDependencySynchronize();   // scores ready

    float logit = -1e9f;
    int   idx   = 0x7FFFFFFF;
    if (live) {
        int e[16] = { r0.x, r0.y, r0.z, r0.w, r1.x, r1.y, r1.z, r1.w,
                      r2.x, r2.y, r2.z, r2.w, r3.x, r3.y, r3.z, r3.w };
        float sum = 0.0f;
        #pragma unroll
        for (int j = 0; j < 16; ++j)
            if (j < my_len) sum += s[e[j]];
        logit = sum / (float)my_len + bias;
        if (my_mask == 0) logit = -1e9f;
        idx = i;
    }

    unsigned long long key =
        ((unsigned long long)f2sortable(logit) << 32) |
        (unsigned long long)(0xFFFFFFFFu - (unsigned)idx);
    float ex = live ? expf(logit) : 0.0f;   // exp(-1e9) == 0 exactly

    #pragma unroll
    for (int o = 16; o; o >>= 1) {
        unsigned long long ok = __shfl_xor_sync(0xFFFFFFFFu, key, o);
        if (ok > key) key = ok;
        ex += __shfl_xor_sync(0xFFFFFFFFu, ex, o);
    }

    if ((t & 31) == 0) {
        skey[t >> 5] = key;
        sex[t >> 5]  = ex;
    }
    __syncthreads();

    if (t < 32) {
        // reduce the 8 per-warp entries inside warp 0
        unsigned long long k2 = (t < 8) ? skey[t] : 0ull;
        float e2 = (t < 8) ? sex[t] : 0.0f;
        #pragma unroll
        for (int o = 4; o; o >>= 1) {
            unsigned long long ok = __shfl_xor_sync(0xFFFFFFFFu, k2, o);
            if (ok > k2) k2 = ok;
            e2 += __shfl_xor_sync(0xFFFFFFFFu, e2, o);
        }
        if (t == 0) {
            atomicMax(&g_key, k2);
            if (e2 > 0.0f) atomicAdd(&g_sumexp, e2);
        }
    }

    cudaTriggerProgrammaticLaunchCompletion();
}

// ---------------------------------------------------------------------------
// Kernel 3 (PDL tertiary, 1 block x 256): decode winner, z[p], output, reset.
// out: [0]=p, [1]=logprob, [2..257]=z[p]
// ---------------------------------------------------------------------------
__global__ void __launch_bounds__(256) finalize_kernel(
        const int* __restrict__ paths,
        const int* __restrict__ path_lens,
        const float* __restrict__ emb,
        int max_len,
        float* __restrict__ out) {
    cudaGridDependencySynchronize();   // all K2 atomics complete

    int t = threadIdx.x;

    unsigned long long fk = g_key;
    float S   = g_sumexp;
    int   p   = (int)(0xFFFFFFFFu - (unsigned)(fk & 0xFFFFFFFFull));
    float l_p = sortable2f((unsigned)(fk >> 32));

    if (t == 0) {
        out[0] = (float)p;
        out[1] = l_p - logf(S);
        g_key = 0ull;                  // reset for next graph replay
        g_sumexp = 0.0f;
    }

    // z[p]: guarded-unroll ragged mean (parallel independent loads)
    int len = path_lens[p] + 1;
    const int4* row4 = reinterpret_cast<const int4*>(paths + (size_t)p * max_len);
    int4 q0 = row4[0], q1 = row4[1], q2 = row4[2], q3 = row4[3];
    int e[16] = { q0.x, q0.y, q0.z, q0.w, q1.x, q1.y, q1.z, q1.w,
                  q2.x, q2.y, q2.z, q2.w, q3.x, q3.y, q3.z, q3.w };
    float acc = 0.0f;
    #pragma unroll
    for (int k = 0; k < 16; ++k) {
        float v = 0.0f;
        if (k < len) v = emb[(size_t)e[k] * 256 + t];
        acc += v;
    }
    out[2 + t] = acc / (float)len;
}

// ---------------------------------------------------------------------------
// Launch: score --PDL--> logits --PDL--> finalize
// Inputs: edge_emb f32[100000,256], paths i32[20000,16], path_lens i32[20000],
//         path_mask i32[20000], W f32[1,256], b f32[1], deterministic i32[1]
// ---------------------------------------------------------------------------
extern "C" void kernel_launch(void* const* d_in, const int* in_sizes, int n_in,
                              void* d_out, int out_size) {
    const float* edge_emb  = (const float*)d_in[0];
    const int*   paths     = (const int*)d_in[1];
    const int*   path_lens = (const int*)d_in[2];
    const int*   path_mask = (const int*)d_in[3];
    const float* W         = (const float*)d_in[4];
    const float* b         = (const float*)d_in[5];

    int hidden  = in_sizes[4];              // 256
    int n_edges = in_sizes[0] / hidden;     // 100000
    int n_paths = in_sizes[2];              // 20000
    int max_len = in_sizes[1] / n_paths;    // 16

    float* out = (float*)d_out;

    float* scores; cudaGetSymbolAddress((void**)&scores, g_scores);

    cudaLaunchAttribute pdl[1];
    pdl[0].id = cudaLaunchAttributeProgrammaticStreamSerialization;
    pdl[0].val.programmaticStreamSerializationAllowed = 1;

    // K1: frozen score winner
    {
        int edges_per_block = 16;
        int blocks = (n_edges + edges_per_block - 1) / edges_per_block;
        score_kernel<<<blocks, 256>>>(edge_emb, W, scores, n_edges);
    }

    // K2: logits + block-aggregated atomics (PDL secondary)
    {
        int nb2 = (n_paths + 255) / 256;    // 79
        cudaLaunchConfig_t cfg = {};
        cfg.gridDim  = dim3((unsigned)nb2, 1, 1);
        cfg.blockDim = dim3(256, 1, 1);
        cfg.stream = 0;
        cfg.attrs = pdl;
        cfg.numAttrs = 1;
        cudaLaunchKernelEx(&cfg, logits_kernel,
                           paths, path_lens, path_mask,
                           (const float*)scores, b, n_paths, max_len);
    }

    // K3: finalize (PDL tertiary, 1 block)
    {
        cudaLaunchConfig_t cfg = {};
        cfg.gridDim  = dim3(1, 1, 1);
        cfg.blockDim = dim3(256, 1, 1);
        cfg.stream = 0;
        cfg.attrs = pdl;
        cfg.numAttrs = 1;
        cudaLaunchKernelEx(&cfg, finalize_kernel,
                           paths, path_lens, edge_emb, max_len, out);
    }
}

// round 17
// speedup vs baseline: 1.0202x; 1.0202x over previous
#include <cuda_runtime.h>
#include <math.h>

#define MAX_EDGES 100000

__device__ float g_scores[MAX_EDGES];
__device__ unsigned long long g_key;    // [sortable(logit):32 | ~idx:32], init 0
__device__ float g_sumexp;              // init 0; finalize resets both

// ---------------------------------------------------------------------------
// Kernel 1: s[e] = dot(edge_emb[e,:256], W)
// 2-tile software pipeline per warp (4 edges): tile1's 4 LDG.128 are issued
// AFTER tile0's loads but BEFORE tile0's reduce, so loads stay in flight
// through the shuffle tail without front-batching 8 (MLP_p1 stays 4).
// smem-staged W (proven winner), lane map {lane, lane+32}.
// ---------------------------------------------------------------------------
__global__ void __launch_bounds__(256) score_kernel(
        const float* __restrict__ emb,
        const float* __restrict__ W,
        float* __restrict__ s,
        int n_edges) {
    __shared__ float4 sw[64];

    int t    = threadIdx.x;
    int lane = t & 31;
    int warp = (blockIdx.x * blockDim.x + t) >> 5;
    int e0 = warp * 4;                 // 4 edges per warp (2 tiles of 2)

    if (t < 64) sw[t] = reinterpret_cast<const float4*>(W)[t];
    __syncthreads();

    if (e0 < n_edges) {
        float4 w0 = sw[lane];
        float4 w1 = sw[lane + 32];

        const float4* p0 = reinterpret_cast<const float4*>(emb + (size_t)e0 * 256);

        // tile 0: edges e0, e0+1  (4 independent LDG.128)
        float4 a0 = p0[lane];
        float4 a1 = p0[lane + 32];
        float4 b0 = p0[64 + lane];
        float4 b1 = p0[64 + lane + 32];

        // tile 1: edges e0+2, e0+3 — issued before tile 0's reduce
        bool have2 = (e0 + 2 < n_edges);
        bool have3 = (e0 + 3 < n_edges);
        float4 z4 = make_float4(0.f, 0.f, 0.f, 0.f);
        float4 c0 = z4, c1 = z4, d0 = z4, d1 = z4;
        if (have2) { c0 = p0[128 + lane]; c1 = p0[128 + lane + 32]; }
        if (have3) { d0 = p0[192 + lane]; d1 = p0[192 + lane + 32]; }

        // reduce tile 0 (tile 1 loads in flight underneath)
        float accA = a0.x*w0.x + a0.y*w0.y + a0.z*w0.z + a0.w*w0.w
                   + a1.x*w1.x + a1.y*w1.y + a1.z*w1.z + a1.w*w1.w;
        float accB = b0.x*w0.x + b0.y*w0.y + b0.z*w0.z + b0.w*w0.w
                   + b1.x*w1.x + b1.y*w1.y + b1.z*w1.z + b1.w*w1.w;
        #pragma unroll
        for (int o = 16; o; o >>= 1) {
            accA += __shfl_xor_sync(0xFFFFFFFFu, accA, o);
            accB += __shfl_xor_sync(0xFFFFFFFFu, accB, o);
        }
        if (lane == 0) {
            s[e0] = accA;
            if (e0 + 1 < n_edges) s[e0 + 1] = accB;
        }

        // reduce tile 1
        if (have2) {
            float accC = c0.x*w0.x + c0.y*w0.y + c0.z*w0.z + c0.w*w0.w
                       + c1.x*w1.x + c1.y*w1.y + c1.z*w1.z + c1.w*w1.w;
            float accD = d0.x*w0.x + d0.y*w0.y + d0.z*w0.z + d0.w*w0.w
                       + d1.x*w1.x + d1.y*w1.y + d1.z*w1.z + d1.w*w1.w;
            #pragma unroll
            for (int o = 16; o; o >>= 1) {
                accC += __shfl_xor_sync(0xFFFFFFFFu, accC, o);
                accD += __shfl_xor_sync(0xFFFFFFFFu, accD, o);
            }
            if (lane == 0) {
                s[e0 + 2] = accC;
                if (have3) s[e0 + 3] = accD;
            }
        }
    }

    cudaTriggerProgrammaticLaunchCompletion();
}

// sortable encoding: preserves float order as unsigned order
__device__ __forceinline__ unsigned int f2sortable(float f) {
    unsigned int u = __float_as_uint(f);
    return (u & 0x80000000u) ? ~u : (u | 0x80000000u);
}
__device__ __forceinline__ float sortable2f(unsigned int u) {
    u = (u & 0x80000000u) ? (u & 0x7FFFFFFFu) : ~u;
    return __uint_as_float(u);
}

// ---------------------------------------------------------------------------
// Kernel 2 (PDL secondary of score): logits + warp reduce + block-aggregated
// atomics (1 atomicMax + 1 atomicAdd per block).   [R15/R16 structure]
// ---------------------------------------------------------------------------
__global__ void __launch_bounds__(256) logits_kernel(
        const int* __restrict__ paths,
        const int* __restrict__ path_lens,
        const int* __restrict__ path_mask,
        const float* __restrict__ s,
        const float* __restrict__ b,
        int n_paths, int max_len) {
    __shared__ unsigned long long skey[8];
    __shared__ float sex[8];

    int t = threadIdx.x;
    int i = blockIdx.x * 256 + t;
    bool live = (i < n_paths);

    // preamble: score-independent loads (overlap primary via PDL)
    int4 r0 = make_int4(0,0,0,0), r1 = r0, r2 = r0, r3 = r0;
    int  my_len = 1, my_mask = 0;
    float bias = 0.0f;
    if (live) {
        const int4* row = reinterpret_cast<const int4*>(paths + (size_t)i * max_len);
        r0 = row[0]; r1 = row[1]; r2 = row[2]; r3 = row[3];
        my_len  = path_lens[i] + 1;
        my_mask = path_mask[i];
        bias    = b[0];
    }

    cudaGridDependencySynchronize();   // scores ready

    float logit = -1e9f;
    int   idx   = 0x7FFFFFFF;
    if (live) {
        int e[16] = { r0.x, r0.y, r0.z, r0.w, r1.x, r1.y, r1.z, r1.w,
                      r2.x, r2.y, r2.z, r2.w, r3.x, r3.y, r3.z, r3.w };
        float sum = 0.0f;
        #pragma unroll
        for (int j = 0; j < 16; ++j)
            if (j < my_len) sum += s[e[j]];
        logit = sum / (float)my_len + bias;
        if (my_mask == 0) logit = -1e9f;
        idx = i;
    }

    unsigned long long key =
        ((unsigned long long)f2sortable(logit) << 32) |
        (unsigned long long)(0xFFFFFFFFu - (unsigned)idx);
    float ex = live ? expf(logit) : 0.0f;   // exp(-1e9) == 0 exactly

    #pragma unroll
    for (int o = 16; o; o >>= 1) {
        unsigned long long ok = __shfl_xor_sync(0xFFFFFFFFu, key, o);
        if (ok > key) key = ok;
        ex += __shfl_xor_sync(0xFFFFFFFFu, ex, o);
    }

    if ((t & 31) == 0) {
        skey[t >> 5] = key;
        sex[t >> 5]  = ex;
    }
    __syncthreads();

    if (t < 32) {
        unsigned long long k2 = (t < 8) ? skey[t] : 0ull;
        float e2 = (t < 8) ? sex[t] : 0.0f;
        #pragma unroll
        for (int o = 4; o; o >>= 1) {
            unsigned long long ok = __shfl_xor_sync(0xFFFFFFFFu, k2, o);
            if (ok > k2) k2 = ok;
            e2 += __shfl_xor_sync(0xFFFFFFFFu, e2, o);
        }
        if (t == 0) {
            atomicMax(&g_key, k2);
            if (e2 > 0.0f) atomicAdd(&g_sumexp, e2);
        }
    }

    cudaTriggerProgrammaticLaunchCompletion();
}

// ---------------------------------------------------------------------------
// Kernel 3 (PDL tertiary, 1 block x 256): decode winner, z[p], output, reset.
// out: [0]=p, [1]=logprob, [2..257]=z[p]
// ---------------------------------------------------------------------------
__global__ void __launch_bounds__(256) finalize_kernel(
        const int* __restrict__ paths,
        const int* __restrict__ path_lens,
        const float* __restrict__ emb,
        int max_len,
        float* __restrict__ out) {
    cudaGridDependencySynchronize();   // all K2 atomics complete

    int t = threadIdx.x;

    unsigned long long fk = g_key;
    float S   = g_sumexp;
    int   p   = (int)(0xFFFFFFFFu - (unsigned)(fk & 0xFFFFFFFFull));
    float l_p = sortable2f((unsigned)(fk >> 32));

    if (t == 0) {
        out[0] = (float)p;
        out[1] = l_p - logf(S);
        g_key = 0ull;                  // reset for next graph replay
        g_sumexp = 0.0f;
    }

    // z[p]: guarded-unroll ragged mean (parallel independent loads)
    int len = path_lens[p] + 1;
    const int4* row4 = reinterpret_cast<const int4*>(paths + (size_t)p * max_len);
    int4 q0 = row4[0], q1 = row4[1], q2 = row4[2], q3 = row4[3];
    int e[16] = { q0.x, q0.y, q0.z, q0.w, q1.x, q1.y, q1.z, q1.w,
                  q2.x, q2.y, q2.z, q2.w, q3.x, q3.y, q3.z, q3.w };
    float acc = 0.0f;
    #pragma unroll
    for (int k = 0; k < 16; ++k) {
        float v = 0.0f;
        if (k < len) v = emb[(size_t)e[k] * 256 + t];
        acc += v;
    }
    out[2 + t] = acc / (float)len;
}

// ---------------------------------------------------------------------------
// Launch: score --PDL--> logits --PDL--> finalize
// Inputs: edge_emb f32[100000,256], paths i32[20000,16], path_lens i32[20000],
//         path_mask i32[20000], W f32[1,256], b f32[1], deterministic i32[1]
// ---------------------------------------------------------------------------
extern "C" void kernel_launch(void* const* d_in, const int* in_sizes, int n_in,
                              void* d_out, int out_size) {
    const float* edge_emb  = (const float*)d_in[0];
    const int*   paths     = (const int*)d_in[1];
    const int*   path_lens = (const int*)d_in[2];
    const int*   path_mask = (const int*)d_in[3];
    const float* W         = (const float*)d_in[4];
    const float* b         = (const float*)d_in[5];

    int hidden  = in_sizes[4];              // 256
    int n_edges = in_sizes[0] / hidden;     // 100000
    int n_paths = in_sizes[2];              // 20000
    int max_len = in_sizes[1] / n_paths;    // 16

    float* out = (float*)d_out;

    float* scores; cudaGetSymbolAddress((void**)&scores, g_scores);

    cudaLaunchAttribute pdl[1];
    pdl[0].id = cudaLaunchAttributeProgrammaticStreamSerialization;
    pdl[0].val.programmaticStreamSerializationAllowed = 1;

    // K1: 4 edges per warp (2-tile pipeline), 8 warps/block -> 3125 blocks
    {
        int edges_per_block = 32;
        int blocks = (n_edges + edges_per_block - 1) / edges_per_block;
        score_kernel<<<blocks, 256>>>(edge_emb, W, scores, n_edges);
    }

    // K2: logits + block-aggregated atomics (PDL secondary)
    {
        int nb2 = (n_paths + 255) / 256;    // 79
        cudaLaunchConfig_t cfg = {};
        cfg.gridDim  = dim3((unsigned)nb2, 1, 1);
        cfg.blockDim = dim3(256, 1, 1);
        cfg.stream = 0;
        cfg.attrs = pdl;
        cfg.numAttrs = 1;
        cudaLaunchKernelEx(&cfg, logits_kernel,
                           paths, path_lens, path_mask,
                           (const float*)scores, b, n_paths, max_len);
    }

    // K3: finalize (PDL tertiary, 1 block)
    {
        cudaLaunchConfig_t cfg = {};
        cfg.gridDim  = dim3(1, 1, 1);
        cfg.blockDim = dim3(256, 1, 1);
        cfg.stream = 0;
        cfg.attrs = pdl;
        cfg.numAttrs = 1;
        cudaLaunchKernelEx(&cfg, finalize_kernel,
                           paths, path_lens, edge_emb, max_len, out);
    }
}